// round 15
// baseline (speedup 1.0000x reference)
#include <cuda_runtime.h>
#include <cuda_bf16.h>
#include <cstdint>

#define NSTEP 730
#define NG    2000
#define MU    16
#define NOUT  500
#define PRECS 1e-5f

#define SPf 96000   // params stride per t, in floats (NG*3*MU)
#define SXf 6000    // x stride per t, in floats (NG*3)
#define NLANE 32000 // NG*MU

// Reduced flow: qA[t][g] = mean_mu(Q0+Q1+Q2) * Ai[g]
__device__ float g_qA[NSTEP * NG];

__device__ __forceinline__ float f_lg2(float v) {
    float y; asm("lg2.approx.f32 %0, %1;" : "=f"(y) : "f"(v)); return y;
}
__device__ __forceinline__ float f_ex2(float v) {
    float y; asm("ex2.approx.f32 %0, %1;" : "=f"(y) : "f"(v)); return y;
}
__device__ __forceinline__ uint32_t f_tf32(float v) {
    uint32_t u; asm("cvt.rna.tf32.f32 %0, %1;" : "=r"(u) : "f"(v)); return u;
}

// ---------------------------------------------------------------------------
// Kernel 1: HBV scan — R14 converged version (~162us), UNCHANGED.
// ---------------------------------------------------------------------------
__global__ __launch_bounds__(256)
void hbv_scan_kernel(const float* __restrict__ x,          // (730, 2000, 3)
                     const float* __restrict__ params,     // (730, 2000, 3, 16)
                     const float* __restrict__ wl,         // (2000, 13, 16)
                     const float* __restrict__ Ai,         // (2000,)
                     const float* __restrict__ Acb,        // (2000,)
                     float* __restrict__ out)              // (730, 500) — zeroed here
{
    int tid = blockIdx.x * 256 + threadIdx.x;   // in [0, 32000)
    int g = tid >> 4;
    int m = tid & 15;

    // ---- zero the output (poisoned to 0xAA; GEMM accumulates with atomics).
    for (int i = tid; i < NSTEP * NOUT; i += NLANE) out[i] = 0.0f;

    // ---- per-(g,m) waterloss parameters, scaled by SCA2 ----
    const float* w = wl + (size_t)g * 13 * MU + m;
    float parFC    = 50.0f   + w[0  * MU] * (1000.0f - 50.0f);
    float parK1    = 0.01f   + w[1  * MU] * (0.5f   - 0.01f);
    float parK2    = 0.001f  + w[2  * MU] * (0.2f   - 0.001f);
    float parLP    = 0.2f    + w[3  * MU] * (1.0f   - 0.2f);
    float parPERC  =           w[4  * MU] * 10.0f;
    float parUZL   =           w[5  * MU] * 100.0f;
    float parTT    = -2.5f   + w[6  * MU] * 5.0f;
    float parCFMAX = 0.5f    + w[7  * MU] * (10.0f  - 0.5f);
    float parCFR   =           w[8  * MU] * 0.1f;
    float parCWH   =           w[9  * MU] * 0.2f;
    float parC     =           w[10 * MU] * 1.0f;
    float parTR    =           w[11 * MU] * 20.0f;
    float parAc    =           w[12 * MU] * 2500.0f;

    float Ac  = Acb[g];
    float Aig = Ai[g] * 0.0625f;

    float rf;
    {
        float c1 = fminf(fmaxf((Ac - parAc) * (1.0f / 1000.0f), -1.0f), 1.0f);
        float ea = fminf(fmaxf(-(Ac - 2500.0f) * (1.0f / 50.0f), -10.0f), 0.0f);
        float e  = expf(ea);
        rf = (Ac < 2500.0f) ? (c1 * parTR) : (e * parTR);
    }

    float invFC   = 1.0f / parFC;
    float invLPFC = 1.0f / (parLP * parFC);
    float CFRCF   = parCFR * parCFMAX;
    float lgFC    = f_lg2(invFC);
    float lgLPFC  = f_lg2(invLPFC);

    float SNOWPACK = 0.001f, MELTWATER = 0.001f, SM = 0.001f, SUZ = 0.001f, SLZ = 0.001f;

    const float* pp = params + g * 48 + m;
    const float* xp = x + g * 3;

    float cB[4], cK[4], cBE[4], cP[4], cT[4], cE[4], cLE[4];

    #pragma unroll
    for (int u = 0; u < 4; u++) {
        cB[u]  = __ldcs(pp + u * SPf);
        cK[u]  = __ldcs(pp + u * SPf + 16);
        cBE[u] = __ldcs(pp + u * SPf + 32);
        cP[u]  = xp[u * SXf + 0];
        cT[u]  = xp[u * SXf + 1];
        cE[u]  = xp[u * SXf + 2];
        cLE[u] = f_lg2(cE[u]);
    }

    const float* pf = pp + 4 * SPf;
    const float* xf = xp + 4 * SXf;
    float* qrow = g_qA + g;

#define HBV_STEP(rbv, rkv, rbev, Ptv, Ttv, Etv, LEtv, QDST) do {               \
    float parBETA   = fmaf((rbv),  5.0f,  1.0f);                               \
    float parK0     = fmaf((rkv),  0.85f, 0.05f);                              \
    float parBETAET = fmaf((rbev), 4.7f,  0.3f);                               \
    float bc1  = parBETA   * lgFC;                                             \
    float bc2e = fmaf(parBETAET, lgLPFC, (LEtv));                              \
    float pcSLZ = parC * SLZ;                                                  \
    float RAIN = ((Ttv) >= parTT) ? (Ptv) : 0.0f;                              \
    SNOWPACK += (Ptv) - RAIN;                                                  \
    float melt = fminf(fmaxf(parCFMAX * ((Ttv) - parTT), 0.0f), SNOWPACK);     \
    MELTWATER += melt;  SNOWPACK -= melt;                                      \
    float refr = fminf(fmaxf(CFRCF * (parTT - (Ttv)), 0.0f), MELTWATER);       \
    SNOWPACK += refr;   MELTWATER -= refr;                                     \
    float tosoil = fmaxf(MELTWATER - parCWH * SNOWPACK, 0.0f);                 \
    MELTWATER -= tosoil;                                                       \
    float sw = __saturatef(f_ex2(fmaf(parBETA, f_lg2(SM), bc1)));              \
    float rt_ = RAIN + tosoil;                                                 \
    float recharge = rt_ * sw;                                                 \
    SM += rt_ - recharge;                                                      \
    float excess = fmaxf(SM - parFC, 0.0f);                                    \
    SM -= excess;                                                              \
    float etp = f_ex2(fmaf(parBETAET, f_lg2(SM), bc2e));                       \
    float ETact = fminf(fminf(SM, (Etv)), etp);                                \
    SM = SM - ETact;                                                           \
    float capf = fmaxf(fmaf(-SM, invFC, 1.0f), 0.0f);                          \
    float cap = fminf(SLZ, pcSLZ * capf);                                      \
    SM  = SM + cap;                                                            \
    SLZ = SLZ - cap;                                                           \
    SUZ += recharge + excess;                                                  \
    float PERC = fminf(SUZ, parPERC);                                          \
    SUZ -= PERC;                                                               \
    float Q0 = parK0 * fmaxf(SUZ - parUZL, 0.0f);                              \
    SUZ -= Q0;                                                                 \
    float Q1 = parK1 * SUZ;                                                    \
    SUZ -= Q1;                                                                 \
    SLZ = fmaxf(SLZ + PERC + rf, 0.0f);                                        \
    float Q2 = parK2 * SLZ;                                                    \
    SLZ -= Q2;                                                                 \
    float q_ = Q0 + Q1 + Q2;                                                   \
    q_ += __shfl_xor_sync(0xffffffffu, q_, 8);                                 \
    q_ += __shfl_xor_sync(0xffffffffu, q_, 4);                                 \
    q_ += __shfl_xor_sync(0xffffffffu, q_, 2);                                 \
    q_ += __shfl_xor_sync(0xffffffffu, q_, 1);                                 \
    if (m == 0) (QDST) = q_ * Aig;                                             \
} while (0)

    for (int tb = 0; tb <= 720; tb += 4) {
        float nB[4], nK[4], nBE[4], nP[4], nT[4], nE[4], nLE[4];
        #pragma unroll
        for (int u = 0; u < 4; u++) {
            nB[u]  = __ldcs(pf + u * SPf);
            nK[u]  = __ldcs(pf + u * SPf + 16);
            nBE[u] = __ldcs(pf + u * SPf + 32);
            nP[u]  = xf[u * SXf + 0];
            nT[u]  = xf[u * SXf + 1];
            nE[u]  = xf[u * SXf + 2];
        }
        pf += 4 * SPf;
        xf += 4 * SXf;
        #pragma unroll
        for (int u = 0; u < 4; u++) nLE[u] = f_lg2(nE[u]);

        #pragma unroll
        for (int u = 0; u < 4; u++)
            HBV_STEP(cB[u], cK[u], cBE[u], cP[u], cT[u], cE[u], cLE[u], qrow[u * NG]);
        qrow += 4 * NG;

        #pragma unroll
        for (int u = 0; u < 4; u++) {
            cB[u] = nB[u]; cK[u] = nK[u]; cBE[u] = nBE[u];
            cP[u] = nP[u]; cT[u] = nT[u]; cE[u]  = nE[u]; cLE[u] = nLE[u];
        }
    }

    float tB0 = __ldcs(pf + 0),   tK0 = __ldcs(pf + 16),        tBE0 = __ldcs(pf + 32);
    float tP0 = xf[0],            tT0 = xf[1],                  tE0  = xf[2];
    float tB1 = __ldcs(pf + SPf), tK1 = __ldcs(pf + SPf + 16),  tBE1 = __ldcs(pf + SPf + 32);
    float tP1 = xf[SXf],          tT1 = xf[SXf + 1],            tE1  = xf[SXf + 2];
    float tLE0 = f_lg2(tE0), tLE1 = f_lg2(tE1);

    #pragma unroll
    for (int u = 0; u < 4; u++)
        HBV_STEP(cB[u], cK[u], cBE[u], cP[u], cT[u], cE[u], cLE[u], qrow[u * NG]);
    HBV_STEP(tB0, tK0, tBE0, tP0, tT0, tE0, tLE0, qrow[4 * NG]);
    HBV_STEP(tB1, tK1, tBE1, tP1, tT1, tE1, tLE1, qrow[5 * NG]);

#undef HBV_STEP
}

// ---------------------------------------------------------------------------
// Kernel 2: tf32 tensor-core GEMM. out[t][o] += sum_g qA[t][g]*idx[g][o]
// Same schedule as the measured-best scalar version (BM=64, BN=64, BK=32,
// 256 threads, split-K=6, 576 blocks) but the math runs on mma.sync
// m16n8k8 tf32: warp grid 2(m) x 4(n), warp tile 32x16 = 2x2 mma tiles.
// tf32 conversion happens once at smem fill. Padded smem strides (36/72)
// make all fragment LDS bank-conflict-free (verified permutations).
// ---------------------------------------------------------------------------
#define BM 64
#define BN 64
#define BK 32
#define SPLITK 6
#define KCHUNK 336   // 336*6 = 2016 >= 2000

#define SA_STRIDE 36   // A-frag bank = (lane + kb) % 32 — permutation
#define SB_STRIDE 72   // B-frag bank = (8*tig + gid + c) % 32 — permutation

__global__ __launch_bounds__(256)
void agg_gemm_kernel(const float* __restrict__ idxm,  // (2000, 500)
                     float* __restrict__ out)         // (730, 500)
{
    __shared__ uint32_t sA[BM * SA_STRIDE];   // m-major tf32 bits: sA[m*36 + k]
    __shared__ uint32_t sB[BK * SB_STRIDE];   // k-major tf32 bits: sB[k*72 + n]

    int bm = blockIdx.y * BM;
    int bn = blockIdx.x * BN;
    int kstart = blockIdx.z * KCHUNK;
    int kend   = min(kstart + KCHUNK, NG);

    int tid  = threadIdx.x;
    int wid  = tid >> 5;
    int lane = tid & 31;
    int wm = wid >> 2;            // 0..1  (m)
    int wn = wid & 3;             // 0..3  (n)
    int warpM = wm * 32;          // warp tile 32(m) x 16(n)
    int warpN = wn * 16;
    int gid = lane >> 2;          // 0..7
    int tig = lane & 3;           // 0..3

    float acc[2][2][4] = {};      // [mtile][ntile][frag]

    for (int k0 = kstart; k0 < kend; k0 += BK) {
        // A tile: 64x32; consecutive threads -> consecutive k (gmem coalesced)
        #pragma unroll
        for (int r = 0; r < 8; r++) {
            int i = tid + 256 * r;
            int mm = i >> 5, kk = i & 31;
            int t = bm + mm, k = k0 + kk;
            float v = (t < NSTEP && k < kend) ? g_qA[(size_t)t * NG + k] : 0.0f;
            sA[mm * SA_STRIDE + kk] = f_tf32(v);
        }
        // B tile: 32x64; consecutive threads -> consecutive n (gmem coalesced)
        #pragma unroll
        for (int r = 0; r < 8; r++) {
            int i = tid + 256 * r;
            int kk = i >> 6, nn = i & 63;
            int k = k0 + kk, o = bn + nn;
            float v = (k < kend && o < NOUT) ? idxm[(size_t)k * NOUT + o] : 0.0f;
            sB[kk * SB_STRIDE + nn] = f_tf32(v);
        }
        __syncthreads();

        #pragma unroll
        for (int ks = 0; ks < 4; ks++) {
            int kb = ks * 8;
            // A fragments: a0=(r,c) a1=(r+8,c) a2=(r,c+4) a3=(r+8,c+4),
            // r = gid, c = tig (within the m16k8 tile).
            uint32_t af[2][4];
            #pragma unroll
            for (int mt = 0; mt < 2; mt++) {
                int r0 = (warpM + mt * 16 + gid) * SA_STRIDE + kb + tig;
                af[mt][0] = sA[r0];
                af[mt][1] = sA[r0 + 8 * SA_STRIDE];
                af[mt][2] = sA[r0 + 4];
                af[mt][3] = sA[r0 + 8 * SA_STRIDE + 4];
            }
            // B fragments: b0=(k=tig, n=gid), b1=(k=tig+4, n=gid).
            uint32_t bf[2][2];
            #pragma unroll
            for (int nt = 0; nt < 2; nt++) {
                int c0 = (kb + tig) * SB_STRIDE + warpN + nt * 8 + gid;
                bf[nt][0] = sB[c0];
                bf[nt][1] = sB[c0 + 4 * SB_STRIDE];
            }
            #pragma unroll
            for (int mt = 0; mt < 2; mt++)
                #pragma unroll
                for (int nt = 0; nt < 2; nt++) {
                    asm volatile(
                        "mma.sync.aligned.m16n8k8.row.col.f32.tf32.tf32.f32 "
                        "{%0,%1,%2,%3}, {%4,%5,%6,%7}, {%8,%9}, {%0,%1,%2,%3};"
                        : "+f"(acc[mt][nt][0]), "+f"(acc[mt][nt][1]),
                          "+f"(acc[mt][nt][2]), "+f"(acc[mt][nt][3])
                        : "r"(af[mt][0]), "r"(af[mt][1]),
                          "r"(af[mt][2]), "r"(af[mt][3]),
                          "r"(bf[nt][0]), "r"(bf[nt][1]));
                }
        }
        __syncthreads();
    }

    // Epilogue: c0=(r, 2*tig), c1=(r, 2*tig+1), c2=(r+8, ...), c3.
    #pragma unroll
    for (int mt = 0; mt < 2; mt++)
        #pragma unroll
        for (int nt = 0; nt < 2; nt++) {
            int row0 = bm + warpM + mt * 16 + gid;
            int col0 = bn + warpN + nt * 8 + 2 * tig;
            if (row0 < NSTEP) {
                if (col0 < NOUT)     atomicAdd(&out[(size_t)row0 * NOUT + col0],     acc[mt][nt][0]);
                if (col0 + 1 < NOUT) atomicAdd(&out[(size_t)row0 * NOUT + col0 + 1], acc[mt][nt][1]);
            }
            if (row0 + 8 < NSTEP) {
                if (col0 < NOUT)     atomicAdd(&out[(size_t)(row0 + 8) * NOUT + col0],     acc[mt][nt][2]);
                if (col0 + 1 < NOUT) atomicAdd(&out[(size_t)(row0 + 8) * NOUT + col0 + 1], acc[mt][nt][3]);
            }
        }
}

// ---------------------------------------------------------------------------
extern "C" void kernel_launch(void* const* d_in, const int* in_sizes, int n_in,
                              void* d_out, int out_size) {
    const float* x      = (const float*)d_in[0];  // (730,2000,3)
    const float* params = (const float*)d_in[1];  // (730,2000,3,16)
    const float* wl     = (const float*)d_in[2];  // (2000,13,16)
    const float* Ai     = (const float*)d_in[3];  // (2000,)
    const float* Acb    = (const float*)d_in[4];  // (2000,)
    const float* idxm   = (const float*)d_in[5];  // (2000,500)
    float* out = (float*)d_out;                   // (730,500,1)

    hbv_scan_kernel<<<125, 256>>>(x, params, wl, Ai, Acb, out);

    dim3 grid((NOUT + BN - 1) / BN, (NSTEP + BM - 1) / BM, SPLITK);
    agg_gemm_kernel<<<grid, 256>>>(idxm, out);
}

// round 16
// speedup vs baseline: 1.0986x; 1.0986x over previous
#include <cuda_runtime.h>
#include <cuda_bf16.h>

#define NSTEP 730
#define NG    2000
#define MU    16
#define NOUT  500
#define PRECS 1e-5f

#define SPf 96000   // params stride per t, in floats (NG*3*MU)
#define SXf 6000    // x stride per t, in floats (NG*3)
#define NLANE 32000 // NG*MU

// Reduced flow: qA[t][g] = mean_mu(Q0+Q1+Q2) * Ai[g]
__device__ float g_qA[NSTEP * NG];

__device__ __forceinline__ float f_lg2(float v) {
    float y; asm("lg2.approx.f32 %0, %1;" : "=f"(y) : "f"(v)); return y;
}
__device__ __forceinline__ float f_ex2(float v) {
    float y; asm("ex2.approx.f32 %0, %1;" : "=f"(y) : "f"(v)); return y;
}

// ---------------------------------------------------------------------------
// Kernel 1: HBV scan — R14 converged version (~162us), UNCHANGED.
// ---------------------------------------------------------------------------
__global__ __launch_bounds__(256)
void hbv_scan_kernel(const float* __restrict__ x,          // (730, 2000, 3)
                     const float* __restrict__ params,     // (730, 2000, 3, 16)
                     const float* __restrict__ wl,         // (2000, 13, 16)
                     const float* __restrict__ Ai,         // (2000,)
                     const float* __restrict__ Acb,        // (2000,)
                     float* __restrict__ out)              // (730, 500) — zeroed here
{
    int tid = blockIdx.x * 256 + threadIdx.x;   // in [0, 32000)
    int g = tid >> 4;
    int m = tid & 15;

    // ---- zero the output (poisoned to 0xAA; GEMM accumulates with atomics).
    for (int i = tid; i < NSTEP * NOUT; i += NLANE) out[i] = 0.0f;

    // ---- per-(g,m) waterloss parameters, scaled by SCA2 ----
    const float* w = wl + (size_t)g * 13 * MU + m;
    float parFC    = 50.0f   + w[0  * MU] * (1000.0f - 50.0f);
    float parK1    = 0.01f   + w[1  * MU] * (0.5f   - 0.01f);
    float parK2    = 0.001f  + w[2  * MU] * (0.2f   - 0.001f);
    float parLP    = 0.2f    + w[3  * MU] * (1.0f   - 0.2f);
    float parPERC  =           w[4  * MU] * 10.0f;
    float parUZL   =           w[5  * MU] * 100.0f;
    float parTT    = -2.5f   + w[6  * MU] * 5.0f;
    float parCFMAX = 0.5f    + w[7  * MU] * (10.0f  - 0.5f);
    float parCFR   =           w[8  * MU] * 0.1f;
    float parCWH   =           w[9  * MU] * 0.2f;
    float parC     =           w[10 * MU] * 1.0f;
    float parTR    =           w[11 * MU] * 20.0f;
    float parAc    =           w[12 * MU] * 2500.0f;

    float Ac  = Acb[g];
    float Aig = Ai[g] * 0.0625f;

    float rf;
    {
        float c1 = fminf(fmaxf((Ac - parAc) * (1.0f / 1000.0f), -1.0f), 1.0f);
        float ea = fminf(fmaxf(-(Ac - 2500.0f) * (1.0f / 50.0f), -10.0f), 0.0f);
        float e  = expf(ea);
        rf = (Ac < 2500.0f) ? (c1 * parTR) : (e * parTR);
    }

    float invFC   = 1.0f / parFC;
    float invLPFC = 1.0f / (parLP * parFC);
    float CFRCF   = parCFR * parCFMAX;
    float lgFC    = f_lg2(invFC);
    float lgLPFC  = f_lg2(invLPFC);

    float SNOWPACK = 0.001f, MELTWATER = 0.001f, SM = 0.001f, SUZ = 0.001f, SLZ = 0.001f;

    const float* pp = params + g * 48 + m;
    const float* xp = x + g * 3;

    float cB[4], cK[4], cBE[4], cP[4], cT[4], cE[4], cLE[4];

    #pragma unroll
    for (int u = 0; u < 4; u++) {
        cB[u]  = __ldcs(pp + u * SPf);
        cK[u]  = __ldcs(pp + u * SPf + 16);
        cBE[u] = __ldcs(pp + u * SPf + 32);
        cP[u]  = xp[u * SXf + 0];
        cT[u]  = xp[u * SXf + 1];
        cE[u]  = xp[u * SXf + 2];
        cLE[u] = f_lg2(cE[u]);
    }

    const float* pf = pp + 4 * SPf;
    const float* xf = xp + 4 * SXf;
    float* qrow = g_qA + g;

#define HBV_STEP(rbv, rkv, rbev, Ptv, Ttv, Etv, LEtv, QDST) do {               \
    float parBETA   = fmaf((rbv),  5.0f,  1.0f);                               \
    float parK0     = fmaf((rkv),  0.85f, 0.05f);                              \
    float parBETAET = fmaf((rbev), 4.7f,  0.3f);                               \
    float bc1  = parBETA   * lgFC;                                             \
    float bc2e = fmaf(parBETAET, lgLPFC, (LEtv));                              \
    float pcSLZ = parC * SLZ;                                                  \
    float RAIN = ((Ttv) >= parTT) ? (Ptv) : 0.0f;                              \
    SNOWPACK += (Ptv) - RAIN;                                                  \
    float melt = fminf(fmaxf(parCFMAX * ((Ttv) - parTT), 0.0f), SNOWPACK);     \
    MELTWATER += melt;  SNOWPACK -= melt;                                      \
    float refr = fminf(fmaxf(CFRCF * (parTT - (Ttv)), 0.0f), MELTWATER);       \
    SNOWPACK += refr;   MELTWATER -= refr;                                     \
    float tosoil = fmaxf(MELTWATER - parCWH * SNOWPACK, 0.0f);                 \
    MELTWATER -= tosoil;                                                       \
    float sw = __saturatef(f_ex2(fmaf(parBETA, f_lg2(SM), bc1)));              \
    float rt_ = RAIN + tosoil;                                                 \
    float recharge = rt_ * sw;                                                 \
    SM += rt_ - recharge;                                                      \
    float excess = fmaxf(SM - parFC, 0.0f);                                    \
    SM -= excess;                                                              \
    float etp = f_ex2(fmaf(parBETAET, f_lg2(SM), bc2e));                       \
    float ETact = fminf(fminf(SM, (Etv)), etp);                                \
    SM = SM - ETact;                                                           \
    float capf = fmaxf(fmaf(-SM, invFC, 1.0f), 0.0f);                          \
    float cap = fminf(SLZ, pcSLZ * capf);                                      \
    SM  = SM + cap;                                                            \
    SLZ = SLZ - cap;                                                           \
    SUZ += recharge + excess;                                                  \
    float PERC = fminf(SUZ, parPERC);                                          \
    SUZ -= PERC;                                                               \
    float Q0 = parK0 * fmaxf(SUZ - parUZL, 0.0f);                              \
    SUZ -= Q0;                                                                 \
    float Q1 = parK1 * SUZ;                                                    \
    SUZ -= Q1;                                                                 \
    SLZ = fmaxf(SLZ + PERC + rf, 0.0f);                                        \
    float Q2 = parK2 * SLZ;                                                    \
    SLZ -= Q2;                                                                 \
    float q_ = Q0 + Q1 + Q2;                                                   \
    q_ += __shfl_xor_sync(0xffffffffu, q_, 8);                                 \
    q_ += __shfl_xor_sync(0xffffffffu, q_, 4);                                 \
    q_ += __shfl_xor_sync(0xffffffffu, q_, 2);                                 \
    q_ += __shfl_xor_sync(0xffffffffu, q_, 1);                                 \
    if (m == 0) (QDST) = q_ * Aig;                                             \
} while (0)

    for (int tb = 0; tb <= 720; tb += 4) {
        float nB[4], nK[4], nBE[4], nP[4], nT[4], nE[4], nLE[4];
        #pragma unroll
        for (int u = 0; u < 4; u++) {
            nB[u]  = __ldcs(pf + u * SPf);
            nK[u]  = __ldcs(pf + u * SPf + 16);
            nBE[u] = __ldcs(pf + u * SPf + 32);
            nP[u]  = xf[u * SXf + 0];
            nT[u]  = xf[u * SXf + 1];
            nE[u]  = xf[u * SXf + 2];
        }
        pf += 4 * SPf;
        xf += 4 * SXf;
        #pragma unroll
        for (int u = 0; u < 4; u++) nLE[u] = f_lg2(nE[u]);

        #pragma unroll
        for (int u = 0; u < 4; u++)
            HBV_STEP(cB[u], cK[u], cBE[u], cP[u], cT[u], cE[u], cLE[u], qrow[u * NG]);
        qrow += 4 * NG;

        #pragma unroll
        for (int u = 0; u < 4; u++) {
            cB[u] = nB[u]; cK[u] = nK[u]; cBE[u] = nBE[u];
            cP[u] = nP[u]; cT[u] = nT[u]; cE[u]  = nE[u]; cLE[u] = nLE[u];
        }
    }

    float tB0 = __ldcs(pf + 0),   tK0 = __ldcs(pf + 16),        tBE0 = __ldcs(pf + 32);
    float tP0 = xf[0],            tT0 = xf[1],                  tE0  = xf[2];
    float tB1 = __ldcs(pf + SPf), tK1 = __ldcs(pf + SPf + 16),  tBE1 = __ldcs(pf + SPf + 32);
    float tP1 = xf[SXf],          tT1 = xf[SXf + 1],            tE1  = xf[SXf + 2];
    float tLE0 = f_lg2(tE0), tLE1 = f_lg2(tE1);

    #pragma unroll
    for (int u = 0; u < 4; u++)
        HBV_STEP(cB[u], cK[u], cBE[u], cP[u], cT[u], cE[u], cLE[u], qrow[u * NG]);
    HBV_STEP(tB0, tK0, tBE0, tP0, tT0, tE0, tLE0, qrow[4 * NG]);
    HBV_STEP(tB1, tK1, tBE1, tP1, tT1, tE1, tLE1, qrow[5 * NG]);

#undef HBV_STEP
}

// ---------------------------------------------------------------------------
// Kernel 2: out[t][o] += sum_{g in chunk} qA[t][g] * idx[g][o]
// Scalar-FFMA SGEMM (reverted from tf32 — measured 55.6us winner structure),
// retiled: BK=40, SPLITK=10, KCHUNK=200 = exactly 5 tiles of 40 per chunk.
// No ragged tiles, no k-bounds checks in the steady state; 960 blocks.
// k-major sA with LDS.128 A-fragment broadcast loads.
// ---------------------------------------------------------------------------
#define BM 64
#define BN 64
#define BK 40
#define SPLITK 10
#define KCHUNK 200   // 200*10 = 2000 exactly; 200 = 5 * BK

__global__ __launch_bounds__(256)
void agg_gemm_kernel(const float* __restrict__ idxm,  // (2000, 500)
                     float* __restrict__ out)         // (730, 500)
{
    __shared__ float sA[BK][BM + 4];   // k-major; row stride 68 floats (16B mult)
    __shared__ float sB[BK][BN];       // k-major

    int bm = blockIdx.y * BM;
    int bn = blockIdx.x * BN;
    int kstart = blockIdx.z * KCHUNK;
    int kend   = kstart + KCHUNK;      // always <= NG

    int tid = threadIdx.x;
    int tx = tid & 15;   // n groups of 4
    int ty = tid >> 4;   // m groups of 4

    float acc[4][4] = {};

    for (int k0 = kstart; k0 < kend; k0 += BK) {
        // A tile: 64 x 40. Consecutive threads -> consecutive kk (coalesced).
        // No k bounds check needed (chunk is an exact multiple of BK).
        #pragma unroll
        for (int r = 0; r < 10; r++) {
            int i = tid + 256 * r;
            int mm = i / BK;
            int kk = i % BK;
            int t = bm + mm;
            sA[kk][mm] = (t < NSTEP) ? g_qA[(size_t)t * NG + k0 + kk] : 0.0f;
        }
        // B tile: 40 x 64. Consecutive threads -> consecutive nn (coalesced).
        #pragma unroll
        for (int r = 0; r < 10; r++) {
            int i = tid + 256 * r;
            int kk = i >> 6;
            int nn = i & 63;
            int o = bn + nn;
            sB[kk][nn] = (o < NOUT) ? idxm[(size_t)(k0 + kk) * NOUT + o] : 0.0f;
        }
        __syncthreads();

        #pragma unroll 8
        for (int k = 0; k < BK; k++) {
            float4 a4 = *reinterpret_cast<const float4*>(&sA[k][ty * 4]);
            float4 b4 = *reinterpret_cast<const float4*>(&sB[k][tx * 4]);
            float aa[4] = {a4.x, a4.y, a4.z, a4.w};
            float bb[4] = {b4.x, b4.y, b4.z, b4.w};
            #pragma unroll
            for (int i = 0; i < 4; i++)
                #pragma unroll
                for (int j = 0; j < 4; j++)
                    acc[i][j] = fmaf(aa[i], bb[j], acc[i][j]);
        }
        __syncthreads();
    }

    #pragma unroll
    for (int i = 0; i < 4; i++) {
        int t = bm + ty * 4 + i;
        if (t >= NSTEP) continue;
        #pragma unroll
        for (int j = 0; j < 4; j++) {
            int o = bn + tx * 4 + j;
            if (o < NOUT) atomicAdd(&out[(size_t)t * NOUT + o], acc[i][j]);
        }
    }
}

// ---------------------------------------------------------------------------
extern "C" void kernel_launch(void* const* d_in, const int* in_sizes, int n_in,
                              void* d_out, int out_size) {
    const float* x      = (const float*)d_in[0];  // (730,2000,3)
    const float* params = (const float*)d_in[1];  // (730,2000,3,16)
    const float* wl     = (const float*)d_in[2];  // (2000,13,16)
    const float* Ai     = (const float*)d_in[3];  // (2000,)
    const float* Acb    = (const float*)d_in[4];  // (2000,)
    const float* idxm   = (const float*)d_in[5];  // (2000,500)
    float* out = (float*)d_out;                   // (730,500,1)

    hbv_scan_kernel<<<125, 256>>>(x, params, wl, Ai, Acb, out);

    dim3 grid((NOUT + BN - 1) / BN, (NSTEP + BM - 1) / BM, SPLITK);
    agg_gemm_kernel<<<grid, 256>>>(idxm, out);
}

// round 17
// speedup vs baseline: 1.2336x; 1.1229x over previous
#include <cuda_runtime.h>
#include <cuda_bf16.h>

#define NSTEP 730
#define NG    2000
#define MU    16
#define NOUT  500
#define PRECS 1e-5f

#define SPf 96000   // params stride per t, in floats (NG*3*MU)
#define SXf 6000    // x stride per t, in floats (NG*3)
#define NLANE 32000 // NG*MU

// Reduced flow: qA[t][g] = mean_mu(Q0+Q1+Q2) * Ai[g]
__device__ float g_qA[NSTEP * NG];

__device__ __forceinline__ float f_lg2(float v) {
    float y; asm("lg2.approx.f32 %0, %1;" : "=f"(y) : "f"(v)); return y;
}
__device__ __forceinline__ float f_ex2(float v) {
    float y; asm("ex2.approx.f32 %0, %1;" : "=f"(y) : "f"(v)); return y;
}

// ---------------------------------------------------------------------------
// Kernel 1: HBV scan. 125 x 256 = 32,000 lanes, 1 block/SM.
// R14 step math, but prefetch distance EIGHT steps via 3 rotating register
// buffers (12 steps per iteration): loads for rows t+8..t+11 are in flight
// while steps t..t+7 compute. __launch_bounds__(256,1) frees registers
// (no occupancy target) so the 3 buffers don't spill.
// ---------------------------------------------------------------------------
__global__ __launch_bounds__(256, 1)
void hbv_scan_kernel(const float* __restrict__ x,          // (730, 2000, 3)
                     const float* __restrict__ params,     // (730, 2000, 3, 16)
                     const float* __restrict__ wl,         // (2000, 13, 16)
                     const float* __restrict__ Ai,         // (2000,)
                     const float* __restrict__ Acb,        // (2000,)
                     float* __restrict__ out)              // (730, 500) — zeroed here
{
    int tid = blockIdx.x * 256 + threadIdx.x;   // in [0, 32000)
    int g = tid >> 4;
    int m = tid & 15;

    // ---- zero the output (poisoned to 0xAA; GEMM accumulates with atomics).
    for (int i = tid; i < NSTEP * NOUT; i += NLANE) out[i] = 0.0f;

    // ---- per-(g,m) waterloss parameters, scaled by SCA2 ----
    const float* w = wl + (size_t)g * 13 * MU + m;
    float parFC    = 50.0f   + w[0  * MU] * (1000.0f - 50.0f);
    float parK1    = 0.01f   + w[1  * MU] * (0.5f   - 0.01f);
    float parK2    = 0.001f  + w[2  * MU] * (0.2f   - 0.001f);
    float parLP    = 0.2f    + w[3  * MU] * (1.0f   - 0.2f);
    float parPERC  =           w[4  * MU] * 10.0f;
    float parUZL   =           w[5  * MU] * 100.0f;
    float parTT    = -2.5f   + w[6  * MU] * 5.0f;
    float parCFMAX = 0.5f    + w[7  * MU] * (10.0f  - 0.5f);
    float parCFR   =           w[8  * MU] * 0.1f;
    float parCWH   =           w[9  * MU] * 0.2f;
    float parC     =           w[10 * MU] * 1.0f;
    float parTR    =           w[11 * MU] * 20.0f;
    float parAc    =           w[12 * MU] * 2500.0f;

    float Ac  = Acb[g];
    float Aig = Ai[g] * 0.0625f;

    float rf;
    {
        float c1 = fminf(fmaxf((Ac - parAc) * (1.0f / 1000.0f), -1.0f), 1.0f);
        float ea = fminf(fmaxf(-(Ac - 2500.0f) * (1.0f / 50.0f), -10.0f), 0.0f);
        float e  = expf(ea);
        rf = (Ac < 2500.0f) ? (c1 * parTR) : (e * parTR);
    }

    float invFC   = 1.0f / parFC;
    float invLPFC = 1.0f / (parLP * parFC);
    float CFRCF   = parCFR * parCFMAX;
    float lgFC    = f_lg2(invFC);
    float lgLPFC  = f_lg2(invLPFC);

    float SNOWPACK = 0.001f, MELTWATER = 0.001f, SM = 0.001f, SUZ = 0.001f, SLZ = 0.001f;

    const float* pf = params + g * 48 + m;   // running param pointer (row 0)
    const float* xf = x + g * 3;             // running x pointer (row 0)
    float* qrow = g_qA + g;                  // output row base

    // Three rotating 4-step buffers (7 floats per step each).
    float b0B[4], b0K[4], b0BE[4], b0P[4], b0T[4], b0E[4], b0LE[4];
    float b1B[4], b1K[4], b1BE[4], b1P[4], b1T[4], b1E[4], b1LE[4];
    float b2B[4], b2K[4], b2BE[4], b2P[4], b2T[4], b2E[4], b2LE[4];

#define LOADB(P_) do {                                                         \
    _Pragma("unroll")                                                          \
    for (int u = 0; u < 4; u++) {                                              \
        P_##B[u]  = __ldcs(pf + u * SPf);                                      \
        P_##K[u]  = __ldcs(pf + u * SPf + 16);                                 \
        P_##BE[u] = __ldcs(pf + u * SPf + 32);                                 \
        P_##P[u]  = xf[u * SXf + 0];                                           \
        P_##T[u]  = xf[u * SXf + 1];                                           \
        P_##E[u]  = xf[u * SXf + 2];                                           \
    }                                                                          \
    pf += 4 * SPf;  xf += 4 * SXf;                                             \
    _Pragma("unroll")                                                          \
    for (int u = 0; u < 4; u++) P_##LE[u] = f_lg2(P_##E[u]);                   \
} while (0)

#define HBV_STEP(rbv, rkv, rbev, Ptv, Ttv, Etv, LEtv, QDST) do {               \
    float parBETA   = fmaf((rbv),  5.0f,  1.0f);                               \
    float parK0     = fmaf((rkv),  0.85f, 0.05f);                              \
    float parBETAET = fmaf((rbev), 4.7f,  0.3f);                               \
    float bc1  = parBETA   * lgFC;                                             \
    float bc2e = fmaf(parBETAET, lgLPFC, (LEtv));                              \
    float pcSLZ = parC * SLZ;                                                  \
    float RAIN = ((Ttv) >= parTT) ? (Ptv) : 0.0f;                              \
    SNOWPACK += (Ptv) - RAIN;                                                  \
    float melt = fminf(fmaxf(parCFMAX * ((Ttv) - parTT), 0.0f), SNOWPACK);     \
    MELTWATER += melt;  SNOWPACK -= melt;                                      \
    float refr = fminf(fmaxf(CFRCF * (parTT - (Ttv)), 0.0f), MELTWATER);       \
    SNOWPACK += refr;   MELTWATER -= refr;                                     \
    float tosoil = fmaxf(MELTWATER - parCWH * SNOWPACK, 0.0f);                 \
    MELTWATER -= tosoil;                                                       \
    float sw = __saturatef(f_ex2(fmaf(parBETA, f_lg2(SM), bc1)));              \
    float rt_ = RAIN + tosoil;                                                 \
    float recharge = rt_ * sw;                                                 \
    SM += rt_ - recharge;                                                      \
    float excess = fmaxf(SM - parFC, 0.0f);                                    \
    SM -= excess;                                                              \
    float etp = f_ex2(fmaf(parBETAET, f_lg2(SM), bc2e));                       \
    float ETact = fminf(fminf(SM, (Etv)), etp);                                \
    SM = SM - ETact;                                                           \
    float capf = fmaxf(fmaf(-SM, invFC, 1.0f), 0.0f);                          \
    float cap = fminf(SLZ, pcSLZ * capf);                                      \
    SM  = SM + cap;                                                            \
    SLZ = SLZ - cap;                                                           \
    SUZ += recharge + excess;                                                  \
    float PERC = fminf(SUZ, parPERC);                                          \
    SUZ -= PERC;                                                               \
    float Q0 = parK0 * fmaxf(SUZ - parUZL, 0.0f);                              \
    SUZ -= Q0;                                                                 \
    float Q1 = parK1 * SUZ;                                                    \
    SUZ -= Q1;                                                                 \
    SLZ = fmaxf(SLZ + PERC + rf, 0.0f);                                        \
    float Q2 = parK2 * SLZ;                                                    \
    SLZ -= Q2;                                                                 \
    float q_ = Q0 + Q1 + Q2;                                                   \
    q_ += __shfl_xor_sync(0xffffffffu, q_, 8);                                 \
    q_ += __shfl_xor_sync(0xffffffffu, q_, 4);                                 \
    q_ += __shfl_xor_sync(0xffffffffu, q_, 2);                                 \
    q_ += __shfl_xor_sync(0xffffffffu, q_, 1);                                 \
    if (m == 0) (QDST) = q_ * Aig;                                             \
} while (0)

#define COMP4(P_) do {                                                         \
    _Pragma("unroll")                                                          \
    for (int u = 0; u < 4; u++)                                                \
        HBV_STEP(P_##B[u], P_##K[u], P_##BE[u], P_##P[u], P_##T[u],            \
                 P_##E[u], P_##LE[u], qrow[u * NG]);                           \
    qrow += 4 * NG;                                                            \
} while (0)

    // Prologue: rows 0-3, 4-7, 8-11 in flight / resident.
    LOADB(b0);
    LOADB(b1);
    LOADB(b2);

    // 59 iterations x 12 steps = steps 0..707. Each LOADB is issued
    // 8 compute-steps before its buffer is consumed (distance 8).
    for (int it = 0; it < 59; it++) {
        COMP4(b0); LOADB(b0);   // loads rows 12it+12 .. +15
        COMP4(b1); LOADB(b1);   // loads rows 12it+16 .. +19
        COMP4(b2); LOADB(b2);   // loads rows 12it+20 .. +23
    }
    // Buffers: b0=708-711, b1=712-715, b2=716-719; pf -> row 720.

    COMP4(b0); LOADB(b0);       // steps 708-711; loads rows 720-723
    COMP4(b1); LOADB(b1);       // steps 712-715; loads rows 724-727
    COMP4(b2);                  // steps 716-719
    // partial load: rows 728-729 into b2[0..1]
    #pragma unroll
    for (int u = 0; u < 2; u++) {
        b2B[u]  = __ldcs(pf + u * SPf);
        b2K[u]  = __ldcs(pf + u * SPf + 16);
        b2BE[u] = __ldcs(pf + u * SPf + 32);
        b2P[u]  = xf[u * SXf + 0];
        b2T[u]  = xf[u * SXf + 1];
        b2E[u]  = xf[u * SXf + 2];
        b2LE[u] = f_lg2(b2E[u]);
    }
    COMP4(b0);                  // steps 720-723
    COMP4(b1);                  // steps 724-727
    #pragma unroll
    for (int u = 0; u < 2; u++) // steps 728-729
        HBV_STEP(b2B[u], b2K[u], b2BE[u], b2P[u], b2T[u], b2E[u], b2LE[u], qrow[u * NG]);

#undef COMP4
#undef HBV_STEP
#undef LOADB
}

// ---------------------------------------------------------------------------
// Kernel 2: out[t][o] += sum_{g in chunk} qA[t][g] * idx[g][o]
// SGEMM M=730, N=500, K=2000. R13/R14 measured winner (55.1-55.7us): BM=64,
// BN=64, BK=32, 256 threads, 4x4/thread, split-K=6 (576 blocks), k-major sA
// with LDS.128 A-fragment loads. VERBATIM.
// ---------------------------------------------------------------------------
#define BM 64
#define BN 64
#define BK 32
#define SPLITK 6
#define KCHUNK 336   // 336*6 = 2016 >= 2000

__global__ __launch_bounds__(256)
void agg_gemm_kernel(const float* __restrict__ idxm,  // (2000, 500)
                     float* __restrict__ out)         // (730, 500)
{
    __shared__ float sA[BK][BM + 4];   // k-major; row stride 68 floats (16B mult)
    __shared__ float sB[BK][BN];       // k-major

    int bm = blockIdx.y * BM;
    int bn = blockIdx.x * BN;
    int kstart = blockIdx.z * KCHUNK;
    int kend   = min(kstart + KCHUNK, NG);

    int tid = threadIdx.x;
    int tx = tid & 15;   // n groups of 4
    int ty = tid >> 4;   // m groups of 4

    float acc[4][4] = {};

    for (int k0 = kstart; k0 < kend; k0 += BK) {
        // A tile: consecutive threads -> consecutive kk (gmem coalesced).
        #pragma unroll
        for (int i = tid; i < BM * BK; i += 256) {
            int mm = i >> 5;
            int kk = i & 31;
            int t = bm + mm;
            int k = k0 + kk;
            sA[kk][mm] = (t < NSTEP && k < kend) ? g_qA[(size_t)t * NG + k] : 0.0f;
        }
        // B tile: consecutive threads -> consecutive nn (gmem coalesced)
        #pragma unroll
        for (int i = tid; i < BK * BN; i += 256) {
            int kk = i >> 6;
            int nn = i & 63;
            int k = k0 + kk;
            int o = bn + nn;
            sB[kk][nn] = (k < kend && o < NOUT) ? idxm[(size_t)k * NOUT + o] : 0.0f;
        }
        __syncthreads();

        #pragma unroll 8
        for (int k = 0; k < BK; k++) {
            float4 a4 = *reinterpret_cast<const float4*>(&sA[k][ty * 4]);
            float4 b4 = *reinterpret_cast<const float4*>(&sB[k][tx * 4]);
            float aa[4] = {a4.x, a4.y, a4.z, a4.w};
            float bb[4] = {b4.x, b4.y, b4.z, b4.w};
            #pragma unroll
            for (int i = 0; i < 4; i++)
                #pragma unroll
                for (int j = 0; j < 4; j++)
                    acc[i][j] = fmaf(aa[i], bb[j], acc[i][j]);
        }
        __syncthreads();
    }

    #pragma unroll
    for (int i = 0; i < 4; i++) {
        int t = bm + ty * 4 + i;
        if (t >= NSTEP) continue;
        #pragma unroll
        for (int j = 0; j < 4; j++) {
            int o = bn + tx * 4 + j;
            if (o < NOUT) atomicAdd(&out[(size_t)t * NOUT + o], acc[i][j]);
        }
    }
}

// ---------------------------------------------------------------------------
extern "C" void kernel_launch(void* const* d_in, const int* in_sizes, int n_in,
                              void* d_out, int out_size) {
    const float* x      = (const float*)d_in[0];  // (730,2000,3)
    const float* params = (const float*)d_in[1];  // (730,2000,3,16)
    const float* wl     = (const float*)d_in[2];  // (2000,13,16)
    const float* Ai     = (const float*)d_in[3];  // (2000,)
    const float* Acb    = (const float*)d_in[4];  // (2000,)
    const float* idxm   = (const float*)d_in[5];  // (2000,500)
    float* out = (float*)d_out;                   // (730,500,1)

    hbv_scan_kernel<<<125, 256>>>(x, params, wl, Ai, Acb, out);

    dim3 grid((NOUT + BN - 1) / BN, (NSTEP + BM - 1) / BM, SPLITK);
    agg_gemm_kernel<<<grid, 256>>>(idxm, out);
}